// round 14
// baseline (speedup 1.0000x reference)
#include <cuda_runtime.h>
#include <cuda_bf16.h>
#include <cuda_fp16.h>

#define NN   50000
#define NE   800000
#define FIN  128
#define FOUT 64
#define SLOPE 0.2f
#define SCAN_NB 196                 // ceil(NN/256)
#define GEMM_ROWS 16
#define GEMM_NB 3125                // ceil(NN/GEMM_ROWS)
#define CNT_NB 3125                 // NE/256
#define SCAT_NB 3125                // NE/256
#define AGG_NB 1563                 // ceil(NN*8/256)

// ---------------- scratch (__device__ globals; no allocations allowed) -----
__device__ __align__(256) uint4 g_h16[(size_t)NN * 8]; // h fp16: 64 halfs=128B/row
__device__ float    g_asrc[NN];          // h . att_src (fp32)
__device__ float4   g_dinfo[NN];         // (a_dst, sl, start_bits, unused)
__device__ int      g_cnt[NN];           // in-degree (zeroed by agg each run)
__device__ unsigned g_rkd[NE];           // (dst<<16) | rank
__device__ uint2    g_ep[NE];            // per-edge (src, p) dst-sorted
__device__ unsigned g_state[SCAN_NB];    // lookback: state<<30 | value
__device__ int      g_done_scan;         // pipeline barrier counters
__device__ int      g_done_scat;

__device__ __forceinline__ float leaky(float v) { return v > 0.f ? v : SLOPE * v; }

// packed f32x2 helpers (FFMA2 is PTX-only; ptxas never auto-fuses)
__device__ __forceinline__ long long pk2(float lo, float hi) {
    long long r;
    asm("mov.b64 %0, {%1,%2};" : "=l"(r) : "f"(lo), "f"(hi));
    return r;
}
__device__ __forceinline__ void unpk2(long long v, float& lo, float& hi) {
    asm("mov.b64 {%0,%1}, %2;" : "=f"(lo), "=f"(hi) : "l"(v));
}
__device__ __forceinline__ long long ffma2(long long a, long long b, long long c) {
    long long d;
    asm("fma.rn.f32x2 %0, %1, %2, %3;" : "=l"(d) : "l"(a), "l"(b), "l"(c));
    return d;
}

__device__ __forceinline__ void cvt8(float* f, uint4 hv) {
    float2 a = __half22float2(*(__half2*)&hv.x);
    float2 b = __half22float2(*(__half2*)&hv.y);
    float2 c = __half22float2(*(__half2*)&hv.z);
    float2 d = __half22float2(*(__half2*)&hv.w);
    f[0] = a.x; f[1] = a.y; f[2] = b.x; f[3] = b.y;
    f[4] = c.x; f[5] = c.y; f[6] = d.x; f[7] = d.y;
}

// ===========================================================================
// FAT1: blocks [0,GEMM_NB) = GEMM role; [GEMM_NB, GEMM_NB+CNT_NB) = count.
//       Roles are data-independent -> no intra-kernel sync needed.
// ===========================================================================
__global__ __launch_bounds__(256) void k_fat1(
    const float* __restrict__ x, const float* __restrict__ W,
    const float* __restrict__ att_src, const float* __restrict__ att_dst,
    const int* __restrict__ ei)
{
    __shared__ long long Wsh[FIN * 32];        // 32 KB
    __shared__ long long Xd[GEMM_ROWS * FIN];  // 16 KB (48 KB total, static)

    int tid = threadIdx.x;

    if (blockIdx.x < GEMM_NB) {
        // ---------------- GEMM role: 8 warps x 2 rows = 16 rows/block ------
        int row0 = blockIdx.x * GEMM_ROWS;

        const float2* W2 = (const float2*)W;
        for (int idx = tid; idx < FIN * 32; idx += 256) {
            float2 wv = W2[idx];
            Wsh[idx] = pk2(wv.x, wv.y);
        }
        for (int idx = tid; idx < GEMM_ROWS * 32; idx += 256) {
            int r = idx >> 5, c = idx & 31;
            int row = row0 + r;
            float4 v = (row < NN) ? ((const float4*)(x + (size_t)row * FIN))[c]
                                  : make_float4(0.f, 0.f, 0.f, 0.f);
            long long* dst = &Xd[r * FIN + c * 4];
            dst[0] = pk2(v.x, v.x); dst[1] = pk2(v.y, v.y);
            dst[2] = pk2(v.z, v.z); dst[3] = pk2(v.w, v.w);
        }
        __syncthreads();

        int lane = tid & 31, w = tid >> 5;     // w in 0..7
        float2 as2 = ((const float2*)att_src)[lane];
        float2 ad2 = ((const float2*)att_dst)[lane];

        long long acc[2] = {0, 0};
        #pragma unroll 4
        for (int k = 0; k < FIN; k += 2) {
            long long w0 = Wsh[k * 32 + lane];
            long long w1 = Wsh[(k + 1) * 32 + lane];
            #pragma unroll
            for (int r = 0; r < 2; r++) {
                longlong2 xx = *(const longlong2*)&Xd[(w * 2 + r) * FIN + k];
                acc[r] = ffma2(xx.x, w0, acc[r]);
                acc[r] = ffma2(xx.y, w1, acc[r]);
            }
        }

        #pragma unroll
        for (int r = 0; r < 2; r++) {
            int row = row0 + w * 2 + r;
            if (row >= NN) continue;
            float a0, a1; unpk2(acc[r], a0, a1);
            ((__half2*)&g_h16[(size_t)row * 8])[lane] = __floats2half2_rn(a0, a1);
            float ps = a0 * as2.x + a1 * as2.y;
            float pd = a0 * ad2.x + a1 * ad2.y;
            #pragma unroll
            for (int off = 16; off; off >>= 1) {
                ps += __shfl_xor_sync(0xffffffffu, ps, off);
                pd += __shfl_xor_sync(0xffffffffu, pd, off);
            }
            if (lane == 0) {
                g_asrc[row] = ps;
                *(float2*)&g_dinfo[row] = make_float2(pd, leaky(ps + pd));
            }
        }
    } else {
        // ---------------- count role ---------------------------------------
        int b = blockIdx.x - GEMM_NB;
        if (b == 0) {
            if (tid == 0) { g_done_scan = 0; g_done_scat = 0; }
            if (tid < SCAN_NB) g_state[tid] = 0;
        }
        int i = b * 256 + tid;
        if (i < NE) {
            int d = ei[NE + i];
            unsigned r = (unsigned)atomicAdd(&g_cnt[d], 1);
            g_rkd[i] = ((unsigned)d << 16) | (r & 0xffffu);
        }
    }
}

// ===========================================================================
// FAT2: blocks [0,196) scan -> [196,3321) scatter -> [3321,4884) agg,
//       chained by in-kernel barrier counters (in-order CTA dispatch).
// ===========================================================================
__global__ __launch_bounds__(256) void k_fat2(
    const int* __restrict__ ei, float* __restrict__ out,
    const float* __restrict__ bias)
{
    int tid = threadIdx.x;

    if (blockIdx.x < SCAN_NB) {
        // ---------------- scan role (decoupled lookback) --------------------
        __shared__ int sm[256];
        __shared__ int s_prefix;
        int b = blockIdx.x;
        int idx = b * 256 + tid;
        int v = (idx < NN) ? g_cnt[idx] : 0;
        sm[tid] = v;
        __syncthreads();
        #pragma unroll
        for (int off = 1; off < 256; off <<= 1) {
            int u = (tid >= off) ? sm[tid - off] : 0;
            __syncthreads();
            sm[tid] += u;
            __syncthreads();
        }
        int incl = sm[tid];
        int agg  = sm[255];

        if (tid == 0) {
            if (b == 0) {
                atomicExch(&g_state[0], (2u << 30) | (unsigned)agg);
                s_prefix = 0;
            } else {
                atomicExch(&g_state[b], (1u << 30) | (unsigned)agg);
                int pre = 0, j = b - 1;
                while (true) {
                    unsigned s = atomicAdd(&g_state[j], 0u);
                    unsigned st = s >> 30;
                    if (st == 0u) continue;
                    pre += (int)(s & 0x3fffffffu);
                    if (st == 2u) break;
                    j--;
                }
                s_prefix = pre;
                atomicExch(&g_state[b], (2u << 30) | (unsigned)(pre + agg));
            }
        }
        __syncthreads();
        if (idx < NN) *(int*)&g_dinfo[idx].z = s_prefix + incl - v;
        __syncthreads();
        __threadfence();
        if (tid == 0) atomicAdd(&g_done_scan, 1);

    } else if (blockIdx.x < SCAN_NB + SCAT_NB) {
        // ---------------- scatter role --------------------------------------
        if (tid == 0)
            while (atomicAdd(&g_done_scan, 0) < SCAN_NB) __nanosleep(128);
        __syncthreads();

        int i = (blockIdx.x - SCAN_NB) * 256 + tid;
        if (i < NE) {
            int s = ei[i];
            unsigned rd = g_rkd[i];
            int d = (int)(rd >> 16), rank = (int)(rd & 0xffffu);
            float4 di = g_dinfo[d];             // (a_dst, sl, start_bits, -)
            float p = __expf(leaky(g_asrc[s] + di.x) - di.y);
            int pos = __float_as_int(di.z) + rank;
            g_ep[pos] = make_uint2((unsigned)s, __float_as_uint(p));
        }
        __syncthreads();
        __threadfence();
        if (tid == 0) atomicAdd(&g_done_scat, 1);

    } else {
        // ---------------- agg role ------------------------------------------
        if (tid == 0)
            while (atomicAdd(&g_done_scat, 0) < SCAT_NB) __nanosleep(128);
        __syncthreads();

        int gid = ((blockIdx.x - SCAN_NB - SCAT_NB) * 256 + tid) >> 3;
        int f = tid & 7;
        unsigned segmask = 0xFFu << (tid & 24);
        bool live = (gid < NN);
        int node = live ? gid : (NN - 1);

        float4 di = g_dinfo[node];
        int beg = __float_as_int(di.z);
        int cnt = g_cnt[node];

        float ssum = 1.f;                          // self loop: exp(sl-sl)
        float acc[8];
        cvt8(acc, g_h16[(size_t)node * 8 + f]);    // self-loop contribution

        uint2 ev = make_uint2(0u, 0u);             // prefetch batch 0
        if (cnt > 0 && f < cnt) ev = g_ep[beg + f];

        for (int base = 0; base < cnt; base += 8) {
            int nb = cnt - base; if (nb > 8) nb = 8;
            unsigned s = ev.x;
            float p = __uint_as_float(ev.y);
            if (f >= nb) { s = 0u; p = 0.f; }

            ev = make_uint2(0u, 0u);               // prefetch next batch
            int nxt = base + 8;
            if (nxt < cnt && f < cnt - nxt) ev = g_ep[beg + nxt + f];

            for (int j0 = 0; j0 < nb; j0 += 4) {
                uint4 hb[4]; float pp[4];
                #pragma unroll
                for (int u = 0; u < 4; u++) {
                    unsigned ss = __shfl_sync(segmask, s, j0 + u, 8);
                    pp[u]       = __shfl_sync(segmask, p, j0 + u, 8);
                    hb[u]       = g_h16[(size_t)ss * 8 + f];  // 128B line/edge
                }
                #pragma unroll
                for (int u = 0; u < 4; u++) {
                    float pv = pp[u];              // 0 for padded edges
                    ssum += pv;
                    float fb[8]; cvt8(fb, hb[u]);
                    #pragma unroll
                    for (int q = 0; q < 8; q++) acc[q] += pv * fb[q];
                }
            }
        }

        float inv = 1.f / ssum;
        if (live) {
            float4 b0 = ((const float4*)bias)[f * 2];
            float4 b1 = ((const float4*)bias)[f * 2 + 1];
            float4 r0 = make_float4(acc[0] * inv + b0.x, acc[1] * inv + b0.y,
                                    acc[2] * inv + b0.z, acc[3] * inv + b0.w);
            float4 r1 = make_float4(acc[4] * inv + b1.x, acc[5] * inv + b1.y,
                                    acc[6] * inv + b1.z, acc[7] * inv + b1.w);
            ((float4*)(out + (size_t)node * FOUT))[f * 2]     = r0;
            ((float4*)(out + (size_t)node * FOUT))[f * 2 + 1] = r1;
            if (f == 0) g_cnt[node] = 0;           // ready for next run
        }
    }
}

// ---------------------------------------------------------------------------
extern "C" void kernel_launch(void* const* d_in, const int* in_sizes, int n_in,
                              void* d_out, int out_size)
{
    const float* x    = (const float*)d_in[0];
    const int*   ei   = (const int*)  d_in[1];   // [2, NE]: row0=src, row1=dst
    const float* W    = (const float*)d_in[2];
    const float* asrc = (const float*)d_in[3];
    const float* adst = (const float*)d_in[4];
    const float* bias = (const float*)d_in[5];
    float* out = (float*)d_out;

    k_fat1<<<GEMM_NB + CNT_NB, 256>>>(x, W, asrc, adst, ei);
    k_fat2<<<SCAN_NB + SCAT_NB + AGG_NB, 256>>>(ei, out, bias);
}